// round 15
// baseline (speedup 1.0000x reference)
#include <cuda_runtime.h>
#include <cstdint>
#include <math.h>

#define BSZ    4096
#define NIN    784
#define H1     100
#define H2     10
#define TSTEPS 100
#define TBEGIN 20

#define RPB    16               // rows per CTA
#define NBLK   (BSZ / RPB)      // 256 CTAs -> 2 per SM
#define NTH    352              // warps 0-6 consumers (224 thr, 200 MAC), 7-10 producers (128)
#define NCONS  224
#define NPRODT 128
#define BK     28
#define NKT    (NIN / BK)       // 28
#define NSTAGE 6
#define NCELL  (RPB * H2)       // 160
#define NTILES (TSTEPS * NKT)   // 2800
#define STEPELEM (BSZ * NIN)    // 3,211,264

typedef unsigned long long ull;

// xi = u .* x, plain floats (1.28 GB scratch)
__device__ float g_xi[(size_t)TSTEPS * STEPELEM];

// ---- dynamic smem layout (bytes, 16B-aligned fields) ----
#define OFF_A    0                                   // float [NSTAGE][RPB][BK]   = 10752
#define OFF_B    (OFF_A + NSTAGE * RPB * BK * 4)     // float [NSTAGE][BK][H1]    = 67200
#define OFF_O1   (OFF_B + NSTAGE * BK * H1 * 4)     // float [RPB][H1]           = 6400
#define OFF_W2   (OFF_O1 + RPB * H1 * 4)
#define OFF_B1   (OFF_W2 + H1 * H2 * 4)
#define OFF_B2   (OFF_B1 + H1 * 4)
#define OFF_OACC (OFF_B2 + 48)
#define OFF_MBAR (OFF_OACC + NCELL * 4)             // full[6] empty[6]
#define SMEM_TOTAL (OFF_MBAR + 2 * NSTAGE * 8)

// ---- JAX threefry2x32 (20 rounds), exact ----
__device__ __forceinline__ void tf2x32(uint32_t k0, uint32_t k1,
                                       uint32_t c0, uint32_t c1,
                                       uint32_t& o0, uint32_t& o1) {
    const uint32_t ks2 = k0 ^ k1 ^ 0x1BD11BDAu;
    uint32_t x0 = c0 + k0;
    uint32_t x1 = c1 + k1;
#define TF_RND(r) { x0 += x1; x1 = __funnelshift_l(x1, x1, (r)); x1 ^= x0; }
    TF_RND(13) TF_RND(15) TF_RND(26) TF_RND(6)
    x0 += k1;  x1 += ks2 + 1u;
    TF_RND(17) TF_RND(29) TF_RND(16) TF_RND(24)
    x0 += ks2; x1 += k0 + 2u;
    TF_RND(13) TF_RND(15) TF_RND(26) TF_RND(6)
    x0 += k0;  x1 += k1 + 3u;
    TF_RND(17) TF_RND(29) TF_RND(16) TF_RND(24)
    x0 += k1;  x1 += ks2 + 4u;
    TF_RND(13) TF_RND(15) TF_RND(26) TF_RND(6)
    x0 += ks2; x1 += k0 + 5u;
#undef TF_RND
    o0 = x0; o1 = x1;
}

// 4 uniforms, counters idx..idx+3, interleaved chains (bitwise per-element == tf2x32)
__device__ __forceinline__ void tf_uniform4(uint32_t k0, uint32_t k1, uint32_t idx,
                                            float u[4]) {
    const uint32_t ks2 = k0 ^ k1 ^ 0x1BD11BDAu;
    uint32_t x0[4], x1[4];
    #pragma unroll
    for (int j = 0; j < 4; j++) { x0[j] = 0u + k0; x1[j] = (idx + j) + k1; }
#define TF_RND4(r) { _Pragma("unroll") for (int j = 0; j < 4; j++) { \
        x0[j] += x1[j]; x1[j] = __funnelshift_l(x1[j], x1[j], (r)); x1[j] ^= x0[j]; } }
#define TF_KEY4(a, b) { _Pragma("unroll") for (int j = 0; j < 4; j++) { \
        x0[j] += (a); x1[j] += (b); } }
    TF_RND4(13) TF_RND4(15) TF_RND4(26) TF_RND4(6)
    TF_KEY4(k1, ks2 + 1u)
    TF_RND4(17) TF_RND4(29) TF_RND4(16) TF_RND4(24)
    TF_KEY4(ks2, k0 + 2u)
    TF_RND4(13) TF_RND4(15) TF_RND4(26) TF_RND4(6)
    TF_KEY4(k0, k1 + 3u)
    TF_RND4(17) TF_RND4(29) TF_RND4(16) TF_RND4(24)
    TF_KEY4(k1, ks2 + 4u)
    TF_RND4(13) TF_RND4(15) TF_RND4(26) TF_RND4(6)
    TF_KEY4(ks2, k0 + 5u)
#undef TF_RND4
#undef TF_KEY4
    #pragma unroll
    for (int j = 0; j < 4; j++) {
        const uint32_t bits = x0[j] ^ x1[j];
        u[j] = __uint_as_float((bits >> 9) | 0x3f800000u) - 1.0f;
    }
}

#define DUP64(d, f)  asm("mov.b64 %0, {%1, %1};" : "=l"(d) : "r"(__float_as_uint(f)))
#define FMA2(c, a, b) asm("fma.rn.f32x2 %0, %1, %2, %0;" : "+l"(c) : "l"(a), "l"(b))
#define UNPK(lo, hi, v) asm("mov.b64 {%0, %1}, %2;" : "=r"(lo), "=r"(hi) : "l"(v))

__device__ __forceinline__ uint32_t smem_u32(const void* p) {
    return (uint32_t)__cvta_generic_to_shared(p);
}
__device__ __forceinline__ uint32_t elect_one() {
    uint32_t pred;
    asm volatile("{\n\t.reg .pred p;\n\telect.sync _|p, 0xFFFFFFFF;\n\t"
                 "selp.b32 %0, 1, 0, p;\n\t}" : "=r"(pred));
    return pred;
}
#define MBAR_INIT(a, c) \
    asm volatile("mbarrier.init.shared.b64 [%0], %1;" :: "r"(a), "r"(c) : "memory")
#define MBAR_ARRIVE(a) \
    asm volatile("mbarrier.arrive.release.cta.shared::cta.b64 _, [%0];" :: "r"(a) : "memory")
#define MBAR_WAIT(a, ph) do {                                              \
    uint32_t _m = (a), _p = (ph), _done;                                   \
    asm volatile("{\n\t.reg .pred p;\n\t"                                  \
        "mbarrier.try_wait.parity.acquire.cta.shared::cta.b64 p, [%1], %2;\n\t" \
        "selp.b32 %0, 1, 0, p;\n\t}"                                       \
        : "=r"(_done) : "r"(_m), "r"(_p) : "memory");                      \
    if (!_done) {                                                          \
        asm volatile("{\n\t.reg .pred P1;\n\t"                             \
            "WL_%=:\n\t"                                                   \
            "mbarrier.try_wait.parity.acquire.cta.shared::cta.b64 P1, [%0], %1, 0x989680;\n\t" \
            "@P1 bra.uni WD_%=;\n\t"                                       \
            "bra.uni WL_%=;\n\t"                                           \
            "WD_%=:\n\t}" :: "r"(_m), "r"(_p) : "memory");                 \
    }                                                                      \
} while (0)
#define BAR1_224() asm volatile("bar.sync 1, 224;" ::: "memory")
#define CP16(dst, src) \
    asm volatile("cp.async.cg.shared.global [%0], [%1], 16;" \
                 :: "r"(dst), "l"(src) : "memory")
#define CP_ASYNC_MBAR(a) \
    asm volatile("cp.async.mbarrier.arrive.noinc.shared.b64 [%0];" :: "r"(a) : "memory")

// ======== kernel 1: precompute xi[t] = u .* x (plain float) ========
__global__ void __launch_bounds__(256)
rng_all(const float* __restrict__ x)
{
    const int t = blockIdx.y;
    uint32_t key0, key1;
    tf2x32(0u, 42u, 0u, (uint32_t)t, key0, key1);
    float* __restrict__ dst = &g_xi[(size_t)t * STEPELEM];
    const int base = blockIdx.x * 2048;
    #pragma unroll
    for (int g = 0; g < 2; g++) {
        const int idx = base + g * 1024 + threadIdx.x * 4;
        float u[4];
        tf_uniform4(key0, key1, (uint32_t)idx, u);
        const float4 xv = *(const float4*)&x[idx];
        float4 o;
        o.x = __fmul_rn(u[0], xv.x);
        o.y = __fmul_rn(u[1], xv.y);
        o.z = __fmul_rn(u[2], xv.z);
        o.w = __fmul_rn(u[3], xv.w);
        *(float4*)&dst[idx] = o;
    }
}

// ======== kernel 2: persistent 100-step recurrence, cp.async-fed ========
extern __shared__ __align__(16) char dsm[];

__global__ void __launch_bounds__(NTH, 2)
spiking_all(const float* __restrict__ W1, const float* __restrict__ b1,
            const float* __restrict__ W2, const float* __restrict__ b2,
            float* __restrict__ out)
{
    float (*s_a)[RPB][BK]  = reinterpret_cast<float (*)[RPB][BK]>(dsm + OFF_A);
    float (*s_b)[BK][H1]   = reinterpret_cast<float (*)[BK][H1]>(dsm + OFF_B);
    float (*s_outer1)[H1]  = reinterpret_cast<float (*)[H1]>(dsm + OFF_O1);
    float *s_w2   = reinterpret_cast<float*>(dsm + OFF_W2);
    float *s_b1   = reinterpret_cast<float*>(dsm + OFF_B1);
    float *s_b2   = reinterpret_cast<float*>(dsm + OFF_B2);
    float *s_oacc = reinterpret_cast<float*>(dsm + OFF_OACC);
    ull   *s_mbar = reinterpret_cast<ull*>(dsm + OFF_MBAR);

    const int tid = threadIdx.x;
    const int r0  = blockIdx.x * RPB;

    if (tid == 0) {
        #pragma unroll
        for (int s = 0; s < NSTAGE; s++) {
            MBAR_INIT(smem_u32(&s_mbar[s]), NPRODT);       // full: 128 cp.async arrives
            MBAR_INIT(smem_u32(&s_mbar[NSTAGE + s]), 7);   // empty: 7 consumer warps
        }
    }
    for (int i = tid; i < H1 * H2; i += NTH) s_w2[i] = W2[i];
    for (int i = tid; i < H1;      i += NTH) s_b1[i] = b1[i];
    if (tid < H2) s_b2[tid] = b2[tid];
    for (int i = tid; i < RPB * H1; i += NTH) ((float*)s_outer1)[i] = 0.f;
    __syncthreads();

    // ========== producers (warps 7-10): pure cp.async streams ==========
    if (tid >= NCONS) {
        const int ptid = tid - NCONS;        // 0..127
        const int ar   = ptid / 7;           // A: one float4 each (112 active)
        const int aj   = (ptid - ar * 7) * 4;
        int stage = 0, phase = 1;            // parity trick: first empty-wait passes
        for (int gt = 0; gt < NTILES; gt++) {
            const int t  = gt / NKT;
            const int kt = gt - t * NKT;
            const int k0 = kt * BK;
            const float* __restrict__ xi =
                &g_xi[(size_t)t * STEPELEM + (size_t)r0 * NIN + k0];
            MBAR_WAIT(smem_u32(&s_mbar[NSTAGE + stage]), phase);
            // A: 16 rows x 7 float4 = 112 x 16B copies
            if (ptid < 112) {
                CP16(smem_u32(&s_a[stage][ar][aj]),
                     (const void*)&xi[(size_t)ar * NIN + aj]);
            }
            // B: 28 rows x 25 float4 = 700 x 16B copies
            #pragma unroll
            for (int ii = 0; ii < 6; ii++) {
                const int i = ptid + ii * NPRODT;
                if (ii < 5 || i < BK * 25) {
                    const int kk = i / 25, m = i - kk * 25;
                    CP16(smem_u32(&s_b[stage][kk][m * 4]),
                         (const void*)&W1[(k0 + kk) * H1 + m * 4]);
                }
            }
            CP_ASYNC_MBAR(smem_u32(&s_mbar[stage]));   // arrive on completion (.noinc)
            if (++stage == NSTAGE) { stage = 0; phase ^= 1; }
        }
        return;
    }

    // ========== consumers (tid < 224): 200 MAC threads, 2x4 cells each ==========
    // cg = tid>>3 (col group 0..24 active), rg = tid&7; rows owned: rg, rg+8
    // A row stride 112B -> lanes 0-7 hit banks {0,28,24,20,16,12,8,4}: conflict-free
    const int  cg  = tid >> 3;
    const int  rg  = tid & 7;
    const bool mac = (cg < 25);

    float i2R = 0.f, accR = 0.f;          // layer2 cell tid (tid < 160)
    float inn[2][4] = {};
    ull acc2[2][2];
    int stage = 0, phase = 0;

    for (int t = 0; t < TSTEPS; t++) {
        // ---- layer2 on PREVIOUS step's outer1 (delayed semantics), 1 cell/thread ----
        if (tid < NCELL) {
            const int lr = tid / H2, n = tid - (tid / H2) * H2;
            float acc = 0.f;
            const float* __restrict__ po = &s_outer1[lr][0];
            #pragma unroll 4
            for (int j = 0; j < H1; j++)
                acc = __fadd_rn(acc, __fmul_rn(po[j], s_w2[j * H2 + n]));
            const float exc = __fadd_rn(acc, s_b2[n]);
            if (t >= TBEGIN) accR = __fadd_rn(accR, i2R);
            const float pre  = __fadd_rn(exc, __fmul_rn(i2R, 0.9f));
            const float gate = (pre > 1.0f) ? 1.0f : 0.0f;
            i2R = __fsub_rn(pre, __fmul_rn(gate, __fmul_rn(1.5f, pre)));
        }
        if (mac) {
            acc2[0][0] = 0ull; acc2[0][1] = 0ull;
            acc2[1][0] = 0ull; acc2[1][1] = 0ull;
        }
        BAR1_224();   // layer2 reads of s_outer1 done before state update rewrites

        // ---- tile loop ----
        for (int kt = 0; kt < NKT; kt++) {
            MBAR_WAIT(smem_u32(&s_mbar[stage]), phase);   // full[stage]
            if (mac) {
                #pragma unroll
                for (int g = 0; g < BK; g += 4) {
                    float4 a0 = *(const float4*)&s_a[stage][rg    ][g];
                    float4 a1 = *(const float4*)&s_a[stage][rg + 8][g];
                    ulonglong2 B0 = *(const ulonglong2*)&s_b[stage][g + 0][cg * 4];
                    ulonglong2 B1 = *(const ulonglong2*)&s_b[stage][g + 1][cg * 4];
                    ulonglong2 B2 = *(const ulonglong2*)&s_b[stage][g + 2][cg * 4];
                    ulonglong2 B3 = *(const ulonglong2*)&s_b[stage][g + 3][cg * 4];
                    #define MACROW(ai, i_) { \
                        ull dx, dy, dz, dw; \
                        DUP64(dx, ai.x); DUP64(dy, ai.y); DUP64(dz, ai.z); DUP64(dw, ai.w); \
                        FMA2(acc2[i_][0], dx, B0.x); FMA2(acc2[i_][0], dy, B1.x); \
                        FMA2(acc2[i_][0], dz, B2.x); FMA2(acc2[i_][0], dw, B3.x); \
                        FMA2(acc2[i_][1], dx, B0.y); FMA2(acc2[i_][1], dy, B1.y); \
                        FMA2(acc2[i_][1], dz, B2.y); FMA2(acc2[i_][1], dw, B3.y); }
                    MACROW(a0, 0) MACROW(a1, 1)
                    #undef MACROW
                }
            }
            __syncwarp();
            if (elect_one()) MBAR_ARRIVE(smem_u32(&s_mbar[NSTAGE + stage]));
            if (++stage == NSTAGE) { stage = 0; phase ^= 1; }
        }

        // ---- layer1 state update (identical rounding chain per cell, bitwise) ----
        if (mac) {
            #pragma unroll
            for (int i = 0; i < 2; i++) {
                const int lr = rg + i * 8;
                #pragma unroll
                for (int pp = 0; pp < 2; pp++) {
                    uint32_t ulo, uhi;
                    UNPK(ulo, uhi, acc2[i][pp]);
                    #pragma unroll
                    for (int qq = 0; qq < 2; qq++) {
                        const int   c    = cg * 4 + pp * 2 + qq;
                        const float accv = __uint_as_float(qq ? uhi : ulo);
                        const float exc  = __fadd_rn(accv, s_b1[c]);
                        const float pre  = __fadd_rn(exc, __fmul_rn(inn[i][pp * 2 + qq], 0.9f));
                        const float outv = fmaxf(__fsub_rn(pre, 1.0f), 0.f);
                        const float gate = (pre > 1.0f) ? 1.0f : 0.0f;
                        inn[i][pp * 2 + qq] = __fsub_rn(pre, __fmul_rn(gate, __fmul_rn(1.5f, pre)));
                        s_outer1[lr][c] = outv;
                    }
                }
            }
        }
        BAR1_224();   // state-update writes visible to next step's layer2 reads
    }

    // ---- epilogue: log_softmax ----
    if (tid < NCELL) s_oacc[tid] = accR;
    BAR1_224();
    if (tid < RPB) {
        float v[H2];
        float m = -INFINITY;
        #pragma unroll
        for (int n = 0; n < H2; n++) { v[n] = s_oacc[tid * H2 + n]; m = fmaxf(m, v[n]); }
        float s = 0.f;
        #pragma unroll
        for (int n = 0; n < H2; n++) s += expf(v[n] - m);
        const float ls = logf(s);
        #pragma unroll
        for (int n = 0; n < H2; n++) out[(r0 + tid) * H2 + n] = v[n] - m - ls;
    }
}

extern "C" void kernel_launch(void* const* d_in, const int* in_sizes, int n_in,
                              void* d_out, int out_size) {
    const float* x  = (const float*)d_in[0];
    const float* W1 = (const float*)d_in[1];
    const float* b1 = (const float*)d_in[2];
    const float* W2 = (const float*)d_in[3];
    const float* b2 = (const float*)d_in[4];
    cudaFuncSetAttribute(spiking_all, cudaFuncAttributeMaxDynamicSharedMemorySize,
                         SMEM_TOTAL);
    rng_all<<<dim3(STEPELEM / 2048, TSTEPS), 256>>>(x);
    spiking_all<<<NBLK, NTH, SMEM_TOTAL>>>(W1, b1, W2, b2, (float*)d_out);
}

// round 16
// speedup vs baseline: 1.1108x; 1.1108x over previous
#include <cuda_runtime.h>
#include <cstdint>
#include <math.h>

#define BSZ    4096
#define NIN    784
#define H1     100
#define H2     10
#define TSTEPS 100
#define TBEGIN 20

#define RPB    16               // rows per CTA
#define NBLK   (BSZ / RPB)      // 256 CTAs -> 2 per SM
#define NTH    256              // warps 0-3 consumers, 4-7 producers (cp.async)
#define NCONS  128
#define NPRODT 128
#define BK     56
#define NKT    (NIN / BK)       // 14
#define NSTAGE 3
#define NCELL  (RPB * H2)       // 160
#define NTILES (TSTEPS * NKT)   // 1400
#define STEPELEM (BSZ * NIN)    // 3,211,264

typedef unsigned long long ull;

// xi = u .* x, plain floats (1.28 GB scratch)
__device__ float g_xi[(size_t)TSTEPS * STEPELEM];

// ---- dynamic smem layout (bytes, 16B-aligned fields) ----
#define OFF_A    0                                   // float [NSTAGE][RPB][BK]  = 10752
#define OFF_B    (OFF_A + NSTAGE * RPB * BK * 4)     // float [NSTAGE][BK][H1]   = 67200
#define OFF_O1   (OFF_B + NSTAGE * BK * H1 * 4)     // float [RPB][H1]          = 6400
#define OFF_W2   (OFF_O1 + RPB * H1 * 4)
#define OFF_B1   (OFF_W2 + H1 * H2 * 4)
#define OFF_B2   (OFF_B1 + H1 * 4)
#define OFF_OACC (OFF_B2 + 48)
#define OFF_MBAR (OFF_OACC + NCELL * 4)             // full[3] empty[3]
#define SMEM_TOTAL (OFF_MBAR + 2 * NSTAGE * 8)

// ---- JAX threefry2x32 (20 rounds), exact ----
__device__ __forceinline__ void tf2x32(uint32_t k0, uint32_t k1,
                                       uint32_t c0, uint32_t c1,
                                       uint32_t& o0, uint32_t& o1) {
    const uint32_t ks2 = k0 ^ k1 ^ 0x1BD11BDAu;
    uint32_t x0 = c0 + k0;
    uint32_t x1 = c1 + k1;
#define TF_RND(r) { x0 += x1; x1 = __funnelshift_l(x1, x1, (r)); x1 ^= x0; }
    TF_RND(13) TF_RND(15) TF_RND(26) TF_RND(6)
    x0 += k1;  x1 += ks2 + 1u;
    TF_RND(17) TF_RND(29) TF_RND(16) TF_RND(24)
    x0 += ks2; x1 += k0 + 2u;
    TF_RND(13) TF_RND(15) TF_RND(26) TF_RND(6)
    x0 += k0;  x1 += k1 + 3u;
    TF_RND(17) TF_RND(29) TF_RND(16) TF_RND(24)
    x0 += k1;  x1 += ks2 + 4u;
    TF_RND(13) TF_RND(15) TF_RND(26) TF_RND(6)
    x0 += ks2; x1 += k0 + 5u;
#undef TF_RND
    o0 = x0; o1 = x1;
}

// 4 uniforms, counters idx..idx+3, interleaved chains (bitwise per-element == tf2x32)
__device__ __forceinline__ void tf_uniform4(uint32_t k0, uint32_t k1, uint32_t idx,
                                            float u[4]) {
    const uint32_t ks2 = k0 ^ k1 ^ 0x1BD11BDAu;
    uint32_t x0[4], x1[4];
    #pragma unroll
    for (int j = 0; j < 4; j++) { x0[j] = 0u + k0; x1[j] = (idx + j) + k1; }
#define TF_RND4(r) { _Pragma("unroll") for (int j = 0; j < 4; j++) { \
        x0[j] += x1[j]; x1[j] = __funnelshift_l(x1[j], x1[j], (r)); x1[j] ^= x0[j]; } }
#define TF_KEY4(a, b) { _Pragma("unroll") for (int j = 0; j < 4; j++) { \
        x0[j] += (a); x1[j] += (b); } }
    TF_RND4(13) TF_RND4(15) TF_RND4(26) TF_RND4(6)
    TF_KEY4(k1, ks2 + 1u)
    TF_RND4(17) TF_RND4(29) TF_RND4(16) TF_RND4(24)
    TF_KEY4(ks2, k0 + 2u)
    TF_RND4(13) TF_RND4(15) TF_RND4(26) TF_RND4(6)
    TF_KEY4(k0, k1 + 3u)
    TF_RND4(17) TF_RND4(29) TF_RND4(16) TF_RND4(24)
    TF_KEY4(k1, ks2 + 4u)
    TF_RND4(13) TF_RND4(15) TF_RND4(26) TF_RND4(6)
    TF_KEY4(ks2, k0 + 5u)
#undef TF_RND4
#undef TF_KEY4
    #pragma unroll
    for (int j = 0; j < 4; j++) {
        const uint32_t bits = x0[j] ^ x1[j];
        u[j] = __uint_as_float((bits >> 9) | 0x3f800000u) - 1.0f;
    }
}

#define DUP64(d, f)  asm("mov.b64 %0, {%1, %1};" : "=l"(d) : "r"(__float_as_uint(f)))
#define FMA2(c, a, b) asm("fma.rn.f32x2 %0, %1, %2, %0;" : "+l"(c) : "l"(a), "l"(b))
#define UNPK(lo, hi, v) asm("mov.b64 {%0, %1}, %2;" : "=r"(lo), "=r"(hi) : "l"(v))

__device__ __forceinline__ uint32_t smem_u32(const void* p) {
    return (uint32_t)__cvta_generic_to_shared(p);
}
__device__ __forceinline__ uint32_t elect_one() {
    uint32_t pred;
    asm volatile("{\n\t.reg .pred p;\n\telect.sync _|p, 0xFFFFFFFF;\n\t"
                 "selp.b32 %0, 1, 0, p;\n\t}" : "=r"(pred));
    return pred;
}
#define MBAR_INIT(a, c) \
    asm volatile("mbarrier.init.shared.b64 [%0], %1;" :: "r"(a), "r"(c) : "memory")
#define MBAR_ARRIVE(a) \
    asm volatile("mbarrier.arrive.release.cta.shared::cta.b64 _, [%0];" :: "r"(a) : "memory")
#define MBAR_WAIT(a, ph) do {                                              \
    uint32_t _m = (a), _p = (ph), _done;                                   \
    asm volatile("{\n\t.reg .pred p;\n\t"                                  \
        "mbarrier.try_wait.parity.acquire.cta.shared::cta.b64 p, [%1], %2;\n\t" \
        "selp.b32 %0, 1, 0, p;\n\t}"                                       \
        : "=r"(_done) : "r"(_m), "r"(_p) : "memory");                      \
    if (!_done) {                                                          \
        asm volatile("{\n\t.reg .pred P1;\n\t"                             \
            "WL_%=:\n\t"                                                   \
            "mbarrier.try_wait.parity.acquire.cta.shared::cta.b64 P1, [%0], %1, 0x989680;\n\t" \
            "@P1 bra.uni WD_%=;\n\t"                                       \
            "bra.uni WL_%=;\n\t"                                           \
            "WD_%=:\n\t}" :: "r"(_m), "r"(_p) : "memory");                 \
    }                                                                      \
} while (0)
#define BAR1_128() asm volatile("bar.sync 1, 128;" ::: "memory")
#define CP16(dst, src) \
    asm volatile("cp.async.cg.shared.global [%0], [%1], 16;" \
                 :: "r"(dst), "l"(src) : "memory")
#define CP_ASYNC_MBAR(a) \
    asm volatile("cp.async.mbarrier.arrive.noinc.shared.b64 [%0];" :: "r"(a) : "memory")

// ======== kernel 1: precompute xi[t] = u .* x (plain float) ========
__global__ void __launch_bounds__(256)
rng_all(const float* __restrict__ x)
{
    const int t = blockIdx.y;
    uint32_t key0, key1;
    tf2x32(0u, 42u, 0u, (uint32_t)t, key0, key1);
    float* __restrict__ dst = &g_xi[(size_t)t * STEPELEM];
    const int base = blockIdx.x * 2048;
    #pragma unroll
    for (int g = 0; g < 2; g++) {
        const int idx = base + g * 1024 + threadIdx.x * 4;
        float u[4];
        tf_uniform4(key0, key1, (uint32_t)idx, u);
        const float4 xv = *(const float4*)&x[idx];
        float4 o;
        o.x = __fmul_rn(u[0], xv.x);
        o.y = __fmul_rn(u[1], xv.y);
        o.z = __fmul_rn(u[2], xv.z);
        o.w = __fmul_rn(u[3], xv.w);
        *(float4*)&dst[idx] = o;
    }
}

// ======== kernel 2: persistent 100-step recurrence, cp.async-fed ========
extern __shared__ __align__(16) char dsm[];

__global__ void __launch_bounds__(NTH, 2)
spiking_all(const float* __restrict__ W1, const float* __restrict__ b1,
            const float* __restrict__ W2, const float* __restrict__ b2,
            float* __restrict__ out)
{
    float (*s_a)[RPB][BK]  = reinterpret_cast<float (*)[RPB][BK]>(dsm + OFF_A);
    float (*s_b)[BK][H1]   = reinterpret_cast<float (*)[BK][H1]>(dsm + OFF_B);
    float (*s_outer1)[H1]  = reinterpret_cast<float (*)[H1]>(dsm + OFF_O1);
    float *s_w2   = reinterpret_cast<float*>(dsm + OFF_W2);
    float *s_b1   = reinterpret_cast<float*>(dsm + OFF_B1);
    float *s_b2   = reinterpret_cast<float*>(dsm + OFF_B2);
    float *s_oacc = reinterpret_cast<float*>(dsm + OFF_OACC);
    ull   *s_mbar = reinterpret_cast<ull*>(dsm + OFF_MBAR);

    const int tid = threadIdx.x;
    const int r0  = blockIdx.x * RPB;

    if (tid == 0) {
        #pragma unroll
        for (int s = 0; s < NSTAGE; s++) {
            MBAR_INIT(smem_u32(&s_mbar[s]), NPRODT);       // full: 128 cp.async arrives
            MBAR_INIT(smem_u32(&s_mbar[NSTAGE + s]), 4);   // empty: 4 consumer warps
        }
    }
    for (int i = tid; i < H1 * H2; i += NTH) s_w2[i] = W2[i];
    for (int i = tid; i < H1;      i += NTH) s_b1[i] = b1[i];
    if (tid < H2) s_b2[tid] = b2[tid];
    for (int i = tid; i < RPB * H1; i += NTH) ((float*)s_outer1)[i] = 0.f;
    __syncthreads();

    // ========== producers (warps 4-7): pure cp.async streams ==========
    if (tid >= NCONS) {
        const int ptid = tid - NCONS;        // 0..127
        int stage = 0, phase = 1;            // parity trick: first empty-wait passes
        for (int gt = 0; gt < NTILES; gt++) {
            const int t  = gt / NKT;
            const int kt = gt - t * NKT;
            const int k0 = kt * BK;
            const float* __restrict__ xi =
                &g_xi[(size_t)t * STEPELEM + (size_t)r0 * NIN + k0];
            MBAR_WAIT(smem_u32(&s_mbar[NSTAGE + stage]), phase);
            // A: 16 rows x 14 float4 = 224 x 16B copies
            #pragma unroll
            for (int ii = 0; ii < 2; ii++) {
                const int i = ptid + ii * NPRODT;
                if (ii == 0 || i < RPB * (BK / 4)) {
                    const int r = i / (BK / 4), j = i - r * (BK / 4);
                    CP16(smem_u32(&s_a[stage][r][j * 4]),
                         (const void*)&xi[(size_t)r * NIN + j * 4]);
                }
            }
            // B: 56 rows x 25 float4 = 1400 x 16B copies
            #pragma unroll
            for (int ii = 0; ii < 11; ii++) {
                const int i = ptid + ii * NPRODT;
                if (ii < 10 || i < BK * 25) {
                    const int kk = i / 25, m = i - kk * 25;
                    CP16(smem_u32(&s_b[stage][kk][m * 4]),
                         (const void*)&W1[(k0 + kk) * H1 + m * 4]);
                }
            }
            CP_ASYNC_MBAR(smem_u32(&s_mbar[stage]));   // arrive on completion (.noinc)
            if (++stage == NSTAGE) { stage = 0; phase ^= 1; }
        }
        return;
    }

    // ========== consumers (tid < 128) ==========
    // cg = tid>>2 (col group 0..24), q = tid&3; rows owned: q, q+4, q+8, q+12
    // A row stride 224B = 56 words -> q-lane banks {0,24,16,8}: conflict-free LDS.128
    const int  cg  = tid >> 2;
    const int  q   = tid & 3;
    const bool mac = (tid < 100);

    float i2a = 0.f, acca = 0.f, i2b = 0.f, accb = 0.f;   // layer2 cells tid, 128+tid
    float inn[4][4] = {};
    ull acc2[4][2];
    int stage = 0, phase = 0;

    for (int t = 0; t < TSTEPS; t++) {
        // ---- layer2 on PREVIOUS step's outer1 (delayed semantics) ----
        #pragma unroll
        for (int half = 0; half < 2; half++) {
            if (half == 1 && tid >= NCELL - NCONS) break;
            const int o  = half ? (NCONS + tid) : tid;
            const int lr = o / H2, n = o - lr * H2;
            float& i2R  = half ? i2b  : i2a;
            float& accR = half ? accb : acca;
            float acc = 0.f;
            const float* __restrict__ po = &s_outer1[lr][0];
            #pragma unroll 4
            for (int j = 0; j < H1; j++)
                acc = __fadd_rn(acc, __fmul_rn(po[j], s_w2[j * H2 + n]));
            const float exc = __fadd_rn(acc, s_b2[n]);
            if (t >= TBEGIN) accR = __fadd_rn(accR, i2R);
            const float pre  = __fadd_rn(exc, __fmul_rn(i2R, 0.9f));
            const float gate = (pre > 1.0f) ? 1.0f : 0.0f;
            i2R = __fsub_rn(pre, __fmul_rn(gate, __fmul_rn(1.5f, pre)));
        }
        if (mac) {
            #pragma unroll
            for (int i = 0; i < 4; i++) { acc2[i][0] = 0ull; acc2[i][1] = 0ull; }
        }
        BAR1_128();   // layer2 reads of s_outer1 done before state update rewrites

        // ---- tile loop (14 handshakes/step) ----
        for (int kt = 0; kt < NKT; kt++) {
            MBAR_WAIT(smem_u32(&s_mbar[stage]), phase);   // full[stage]
            if (mac) {
                #pragma unroll
                for (int g = 0; g < BK; g += 4) {
                    // A: 1 LDS.128 per owned row (non-dup), dup in-register
                    float4 a0 = *(const float4*)&s_a[stage][q     ][g];
                    float4 a1 = *(const float4*)&s_a[stage][q + 4 ][g];
                    float4 a2 = *(const float4*)&s_a[stage][q + 8 ][g];
                    float4 a3 = *(const float4*)&s_a[stage][q + 12][g];
                    ulonglong2 B0 = *(const ulonglong2*)&s_b[stage][g + 0][cg * 4];
                    ulonglong2 B1 = *(const ulonglong2*)&s_b[stage][g + 1][cg * 4];
                    ulonglong2 B2 = *(const ulonglong2*)&s_b[stage][g + 2][cg * 4];
                    ulonglong2 B3 = *(const ulonglong2*)&s_b[stage][g + 3][cg * 4];
                    #define MACROW(ai, i_) { \
                        ull dx, dy, dz, dw; \
                        DUP64(dx, ai.x); DUP64(dy, ai.y); DUP64(dz, ai.z); DUP64(dw, ai.w); \
                        FMA2(acc2[i_][0], dx, B0.x); FMA2(acc2[i_][0], dy, B1.x); \
                        FMA2(acc2[i_][0], dz, B2.x); FMA2(acc2[i_][0], dw, B3.x); \
                        FMA2(acc2[i_][1], dx, B0.y); FMA2(acc2[i_][1], dy, B1.y); \
                        FMA2(acc2[i_][1], dz, B2.y); FMA2(acc2[i_][1], dw, B3.y); }
                    MACROW(a0, 0) MACROW(a1, 1) MACROW(a2, 2) MACROW(a3, 3)
                    #undef MACROW
                }
            }
            __syncwarp();
            if (elect_one()) MBAR_ARRIVE(smem_u32(&s_mbar[NSTAGE + stage]));
            if (++stage == NSTAGE) { stage = 0; phase ^= 1; }
        }

        // ---- layer1 state update (identical rounding chain, bitwise) ----
        if (mac) {
            #pragma unroll
            for (int i = 0; i < 4; i++) {
                const int lr = q + i * 4;
                #pragma unroll
                for (int pp = 0; pp < 2; pp++) {
                    uint32_t ulo, uhi;
                    UNPK(ulo, uhi, acc2[i][pp]);
                    #pragma unroll
                    for (int qq = 0; qq < 2; qq++) {
                        const int   c    = cg * 4 + pp * 2 + qq;
                        const float accv = __uint_as_float(qq ? uhi : ulo);
                        const float exc  = __fadd_rn(accv, s_b1[c]);
                        const float pre  = __fadd_rn(exc, __fmul_rn(inn[i][pp * 2 + qq], 0.9f));
                        const float outv = fmaxf(__fsub_rn(pre, 1.0f), 0.f);
                        const float gate = (pre > 1.0f) ? 1.0f : 0.0f;
                        inn[i][pp * 2 + qq] = __fsub_rn(pre, __fmul_rn(gate, __fmul_rn(1.5f, pre)));
                        s_outer1[lr][c] = outv;
                    }
                }
            }
        }
        BAR1_128();   // state-update writes visible to next step's layer2 reads
    }

    // ---- epilogue: log_softmax ----
    s_oacc[tid] = acca;
    if (tid < NCELL - NCONS) s_oacc[NCONS + tid] = accb;
    BAR1_128();
    if (tid < RPB) {
        float v[H2];
        float m = -INFINITY;
        #pragma unroll
        for (int n = 0; n < H2; n++) { v[n] = s_oacc[tid * H2 + n]; m = fmaxf(m, v[n]); }
        float s = 0.f;
        #pragma unroll
        for (int n = 0; n < H2; n++) s += expf(v[n] - m);
        const float ls = logf(s);
        #pragma unroll
        for (int n = 0; n < H2; n++) out[(r0 + tid) * H2 + n] = v[n] - m - ls;
    }
}

extern "C" void kernel_launch(void* const* d_in, const int* in_sizes, int n_in,
                              void* d_out, int out_size) {
    const float* x  = (const float*)d_in[0];
    const float* W1 = (const float*)d_in[1];
    const float* b1 = (const float*)d_in[2];
    const float* W2 = (const float*)d_in[3];
    const float* b2 = (const float*)d_in[4];
    cudaFuncSetAttribute(spiking_all, cudaFuncAttributeMaxDynamicSharedMemorySize,
                         SMEM_TOTAL);
    rng_all<<<dim3(STEPELEM / 2048, TSTEPS), 256>>>(x);
    spiking_all<<<NBLK, NTH, SMEM_TOTAL>>>(W1, b1, W2, b2, (float*)d_out);
}